// round 11
// baseline (speedup 1.0000x reference)
#include <cuda_runtime.h>
#include <cuda_bf16.h>
#include <mma.h>
#include <math.h>

using namespace nvcuda;

#define NN 50000
#define NE 800000
#define DH 256
#define NC 40

// ---------------- device scratch (no allocations; referenced directly in device code) ----
__device__ int   g_cnt[NN];
__device__ int   g_ptr[NN + 1];
__device__ int   g_cur[NN];
__device__ int   g_srcs[NE];
__device__ float g_dis[NN];
// +128 rows padding: wmma epilogue stores full 16x16 tiles past M=50000 (up to 50048)
__device__ float g_A[(size_t)(NN + 128) * DH];  // GEMM out (layers 0,1)
__device__ float g_B[(size_t)NN * DH];          // aggregation out (layers 0,1)
__device__ float g_C40[(size_t)NN * NC];        // layer-2 GEMM out
__device__ float g_D40[(size_t)NN * NC];        // layer-2 aggregation out

// ---------------- CSR build (edge_index is int32: row 0 = src, row 1 = dst) ----------------
__global__ void zero_cnt_kernel() {
    int i = blockIdx.x * blockDim.x + threadIdx.x;
    if (i < NN) g_cnt[i] = 0;
}

__global__ void count_deg_kernel(const int* __restrict__ ei) {
    int e = blockIdx.x * blockDim.x + threadIdx.x;
    if (e < NE) {
        int d = ei[NE + e];
        if (d >= 0 && d < NN) atomicAdd(&g_cnt[d], 1);
    }
}

// single-block exclusive scan over g_cnt -> g_ptr / g_cur; g_dis = rsqrt(cnt+1)
__global__ __launch_bounds__(1024) void scan_kernel() {
    __shared__ int s[1024];
    int carry = 0;
    for (int base = 0; base < NN; base += 1024) {
        int i = base + threadIdx.x;
        int v = (i < NN) ? g_cnt[i] : 0;
        s[threadIdx.x] = v;
        __syncthreads();
#pragma unroll
        for (int off = 1; off < 1024; off <<= 1) {
            int t = (threadIdx.x >= off) ? s[threadIdx.x - off] : 0;
            __syncthreads();
            s[threadIdx.x] += t;
            __syncthreads();
        }
        int incl = s[threadIdx.x];
        int total = s[1023];
        int excl = incl - v;
        if (i < NN) {
            g_ptr[i] = carry + excl;
            g_cur[i] = carry + excl;
            g_dis[i] = rsqrtf((float)(v + 1));  // +1 self loop
        }
        carry += total;
        __syncthreads();
    }
    if (threadIdx.x == 0) g_ptr[NN] = carry;
}

__global__ void scatter_kernel(const int* __restrict__ ei) {
    int e = blockIdx.x * blockDim.x + threadIdx.x;
    if (e < NE) {
        int d = ei[NE + e];
        int srcv = ei[e];
        if (d >= 0 && d < NN && srcv >= 0 && srcv < NN) {
            int pos = atomicAdd(&g_cur[d], 1);
            g_srcs[pos] = srcv;
        }
    }
}

// ---------------- WMMA tf32 GEMM: g_A[M,256] = (relu?)A[M,256] @ W[256,256] ----------------
// 128x128 block tile, 8 warps (4x2), warp tile 32x64 (2x4 wmma 16x16), BK=32.
#define BK 32
#define APAD 8
#define LDS_T (BK + APAD)  // 40 floats

__global__ __launch_bounds__(256)
void gemm_tf32_kernel(const float* __restrict__ xext, const float* __restrict__ W,
                      int M, int relu_in, int in_sel) {
    const int K = DH, N = DH;
    const float* A = (in_sel == 0) ? xext : (const float*)g_B;
    float* C = (float*)g_A;

    __shared__ float As[128][LDS_T];  // row-major: As[m][k]
    __shared__ float Bs[128][LDS_T];  // col-major for wmma B: Bs[n][k]

    int tid = threadIdx.x;
    int wid = tid >> 5;
    int wm = wid & 3;   // 0..3 -> M direction (32 rows each)
    int wn = wid >> 2;  // 0..1 -> N direction (64 cols each)
    int bm = blockIdx.y * 128;
    int bn = blockIdx.x * 128;

    wmma::fragment<wmma::accumulator, 16, 16, 8, float> acc[2][4];
#pragma unroll
    for (int i = 0; i < 2; i++)
#pragma unroll
        for (int j = 0; j < 4; j++) wmma::fill_fragment(acc[i][j], 0.0f);

    for (int kt = 0; kt < K; kt += BK) {
        // A tile: 128 rows x 32 k = 1024 float4; 4 per thread. tf32-round at store.
#pragma unroll
        for (int l = 0; l < 4; l++) {
            int f = l * 256 + tid;
            int row = f >> 3;            // 8 float4 per row
            int c4 = (f & 7) * 4;
            int grow = bm + row;
            float4 v = make_float4(0.f, 0.f, 0.f, 0.f);
            if (grow < M) v = *(const float4*)(A + (size_t)grow * K + kt + c4);
            if (relu_in) {
                v.x = fmaxf(v.x, 0.f); v.y = fmaxf(v.y, 0.f);
                v.z = fmaxf(v.z, 0.f); v.w = fmaxf(v.w, 0.f);
            }
            As[row][c4 + 0] = wmma::__float_to_tf32(v.x);
            As[row][c4 + 1] = wmma::__float_to_tf32(v.y);
            As[row][c4 + 2] = wmma::__float_to_tf32(v.z);
            As[row][c4 + 3] = wmma::__float_to_tf32(v.w);
        }
        // B tile: W rows kt..kt+31, cols bn..bn+127 -> Bs[n][k] (transpose in smem)
#pragma unroll
        for (int l = 0; l < 4; l++) {
            int f = l * 256 + tid;
            int k = f >> 5;              // 32 float4 per k-row
            int n4 = (f & 31) * 4;
            float4 v = *(const float4*)(W + (size_t)(kt + k) * N + bn + n4);
            Bs[n4 + 0][k] = wmma::__float_to_tf32(v.x);
            Bs[n4 + 1][k] = wmma::__float_to_tf32(v.y);
            Bs[n4 + 2][k] = wmma::__float_to_tf32(v.z);
            Bs[n4 + 3][k] = wmma::__float_to_tf32(v.w);
        }
        __syncthreads();

#pragma unroll
        for (int kk = 0; kk < BK; kk += 8) {
            wmma::fragment<wmma::matrix_a, 16, 16, 8, wmma::precision::tf32, wmma::row_major> af[2];
            wmma::fragment<wmma::matrix_b, 16, 16, 8, wmma::precision::tf32, wmma::col_major> bf[4];
#pragma unroll
            for (int i = 0; i < 2; i++)
                wmma::load_matrix_sync(af[i], &As[wm * 32 + i * 16][kk], LDS_T);
#pragma unroll
            for (int j = 0; j < 4; j++)
                wmma::load_matrix_sync(bf[j], &Bs[wn * 64 + j * 16][kk], LDS_T);
#pragma unroll
            for (int i = 0; i < 2; i++)
#pragma unroll
                for (int j = 0; j < 4; j++)
                    wmma::mma_sync(acc[i][j], af[i], bf[j], acc[i][j]);
        }
        __syncthreads();
    }

    // epilogue: C is padded (NN+128 rows) so unguarded 16x16 stores are safe
#pragma unroll
    for (int i = 0; i < 2; i++) {
        int row = bm + wm * 32 + i * 16;
#pragma unroll
        for (int j = 0; j < 4; j++) {
            int col = bn + wn * 64 + j * 16;
            wmma::store_matrix_sync(C + (size_t)row * N + col, acc[i][j], N, wmma::mem_row_major);
        }
    }
}

// ---------------- SIMT GEMM for layer 2: g_C40 = relu(g_B) @ W2[256,40] ----------------
__global__ __launch_bounds__(256)
void gemm_small_kernel(const float* __restrict__ W, int M, int N) {
    const int K = DH;
    const float* A = (const float*)g_B;
    float* C = (float*)g_C40;

    __shared__ float As[16][128];
    __shared__ float Bs[16][128];

    int tid = threadIdx.x;
    int bm = blockIdx.y * 128;
    int tx = tid & 15;
    int ty = tid >> 4;

    float acc[8][8];
#pragma unroll
    for (int i = 0; i < 8; i++)
#pragma unroll
        for (int j = 0; j < 8; j++) acc[i][j] = 0.0f;

    for (int kt = 0; kt < K; kt += 16) {
#pragma unroll
        for (int l = 0; l < 2; l++) {
            int f = tid * 2 + l;
            int row = f >> 2;
            int kc = (f & 3) * 4;
            int grow = bm + row;
            float4 v = make_float4(0.f, 0.f, 0.f, 0.f);
            if (grow < M) v = *(const float4*)(A + (size_t)grow * K + kt + kc);
            v.x = fmaxf(v.x, 0.f); v.y = fmaxf(v.y, 0.f);
            v.z = fmaxf(v.z, 0.f); v.w = fmaxf(v.w, 0.f);
            As[kc + 0][row] = v.x;
            As[kc + 1][row] = v.y;
            As[kc + 2][row] = v.z;
            As[kc + 3][row] = v.w;
        }
#pragma unroll
        for (int l = 0; l < 2; l++) {
            int f = tid * 2 + l;
            int kr = f >> 5;
            int col = (f & 31) * 4;
            float4 v = make_float4(0.f, 0.f, 0.f, 0.f);
            if (col + 3 < N) v = *(const float4*)(W + (size_t)(kt + kr) * N + col);
            *(float4*)&Bs[kr][col] = v;
        }
        __syncthreads();

#pragma unroll
        for (int kk = 0; kk < 16; kk++) {
            float a[8], b[8];
            *(float4*)&a[0] = *(float4*)&As[kk][ty * 8];
            *(float4*)&a[4] = *(float4*)&As[kk][ty * 8 + 4];
            *(float4*)&b[0] = *(float4*)&Bs[kk][tx * 8];
            *(float4*)&b[4] = *(float4*)&Bs[kk][tx * 8 + 4];
#pragma unroll
            for (int i = 0; i < 8; i++)
#pragma unroll
                for (int j = 0; j < 8; j++) acc[i][j] += a[i] * b[j];
        }
        __syncthreads();
    }

#pragma unroll
    for (int i = 0; i < 8; i++) {
        int r = bm + ty * 8 + i;
        if (r >= M) continue;
#pragma unroll
        for (int j = 0; j < 8; j += 4) {
            int c = tx * 8 + j;
            if (c + 3 < N) {
                float4 v = make_float4(acc[i][j], acc[i][j + 1], acc[i][j + 2], acc[i][j + 3]);
                *(float4*)(C + (size_t)r * N + c) = v;
            }
        }
    }
}

// ---------------- aggregation (gather): out[d] = b + dis[d]^2*xw[d] + sum dis[s]dis[d]*xw[s]
__global__ __launch_bounds__(256)
void agg256_kernel(const float* __restrict__ bias) {
    const float* xw = (const float*)g_A;
    float* out = (float*)g_B;
    int node = blockIdx.x * (blockDim.x >> 5) + (threadIdx.x >> 5);
    int lane = threadIdx.x & 31;
    if (node >= NN) return;
    int beg = g_ptr[node], end = g_ptr[node + 1];
    float dd = g_dis[node];

    float4 acc0 = make_float4(0.f, 0.f, 0.f, 0.f);
    float4 acc1 = make_float4(0.f, 0.f, 0.f, 0.f);
    for (int i = beg; i < end; i++) {
        int s = g_srcs[i];
        float nrm = g_dis[s] * dd;
        const float4* row = (const float4*)(xw + (size_t)s * DH);
        float4 a = row[lane];
        float4 b = row[lane + 32];
        acc0.x += nrm * a.x; acc0.y += nrm * a.y; acc0.z += nrm * a.z; acc0.w += nrm * a.w;
        acc1.x += nrm * b.x; acc1.y += nrm * b.y; acc1.z += nrm * b.z; acc1.w += nrm * b.w;
    }
    {
        float self = dd * dd;
        const float4* row = (const float4*)(xw + (size_t)node * DH);
        float4 a = row[lane];
        float4 b = row[lane + 32];
        acc0.x += self * a.x; acc0.y += self * a.y; acc0.z += self * a.z; acc0.w += self * a.w;
        acc1.x += self * b.x; acc1.y += self * b.y; acc1.z += self * b.z; acc1.w += self * b.w;
    }
    const float4* bb = (const float4*)bias;
    float4 b0 = bb[lane], b1 = bb[lane + 32];
    acc0.x += b0.x; acc0.y += b0.y; acc0.z += b0.z; acc0.w += b0.w;
    acc1.x += b1.x; acc1.y += b1.y; acc1.z += b1.z; acc1.w += b1.w;
    float4* o = (float4*)(out + (size_t)node * DH);
    o[lane] = acc0;
    o[lane + 32] = acc1;
}

__global__ __launch_bounds__(256)
void agg40_kernel(const float* __restrict__ bias) {
    const float* xw = (const float*)g_C40;
    float* out = (float*)g_D40;
    int node = blockIdx.x * (blockDim.x >> 5) + (threadIdx.x >> 5);
    int lane = threadIdx.x & 31;
    if (node >= NN) return;
    int beg = g_ptr[node], end = g_ptr[node + 1];
    float dd = g_dis[node];
    bool hi = (lane < NC - 32);

    float a0 = 0.f, a1 = 0.f;
    for (int i = beg; i < end; i++) {
        int s = g_srcs[i];
        float nrm = g_dis[s] * dd;
        const float* row = xw + (size_t)s * NC;
        a0 += nrm * row[lane];
        if (hi) a1 += nrm * row[32 + lane];
    }
    {
        float self = dd * dd;
        const float* row = xw + (size_t)node * NC;
        a0 += self * row[lane];
        if (hi) a1 += self * row[32 + lane];
    }
    a0 += bias[lane];
    if (hi) a1 += bias[32 + lane];
    float* o = out + (size_t)node * NC;
    o[lane] = a0;
    if (hi) o[32 + lane] = a1;
}

// ---------------- log_softmax over 40 classes, one warp per row ----------------
__global__ void log_softmax_kernel(float* __restrict__ out) {
    int row = blockIdx.x * (blockDim.x / 32) + (threadIdx.x >> 5);
    int lane = threadIdx.x & 31;
    if (row >= NN) return;
    const float* r = (const float*)g_D40 + (size_t)row * NC;
    float v0 = r[lane];
    float v1 = (lane < NC - 32) ? r[32 + lane] : -INFINITY;
    float mx = fmaxf(v0, v1);
#pragma unroll
    for (int o = 16; o > 0; o >>= 1) mx = fmaxf(mx, __shfl_xor_sync(0xFFFFFFFF, mx, o));
    float s = expf(v0 - mx) + ((lane < NC - 32) ? expf(v1 - mx) : 0.f);
#pragma unroll
    for (int o = 16; o > 0; o >>= 1) s += __shfl_xor_sync(0xFFFFFFFF, s, o);
    float lse = mx + logf(s);
    float* w = out + (size_t)row * NC;
    w[lane] = v0 - lse;
    if (lane < NC - 32) w[32 + lane] = v1 - lse;
}

// ---------------- launch ----------------
extern "C" void kernel_launch(void* const* d_in, const int* in_sizes, int n_in,
                              void* d_out, int out_size) {
    const float* x = (const float*)d_in[0];
    const int* ei = (const int*)d_in[1];   // int32 (JAX demotes int64 without x64)
    const float* W0 = (const float*)d_in[2];
    const float* b0 = (const float*)d_in[3];
    const float* W1 = (const float*)d_in[4];
    const float* b1 = (const float*)d_in[5];
    const float* W2 = (const float*)d_in[6];
    const float* b2 = (const float*)d_in[7];
    float* out = (float*)d_out;

    // CSR build + normalization
    zero_cnt_kernel<<<(NN + 255) / 256, 256>>>();
    count_deg_kernel<<<(NE + 255) / 256, 256>>>(ei);
    scan_kernel<<<1, 1024>>>();
    scatter_kernel<<<(NE + 255) / 256, 256>>>(ei);

    dim3 wmma_grid(DH / 128, (NN + 127) / 128);
    dim3 small_grid(1, (NN + 127) / 128);
    int agg_grid = (NN + 7) / 8;

    // ---- layer 0: g_A = x @ W0 (tf32); agg g_A -> g_B ----
    gemm_tf32_kernel<<<wmma_grid, 256>>>(x, W0, NN, 0, /*in_sel=*/0);
    agg256_kernel<<<agg_grid, 256>>>(b0);

    // ---- layer 1: g_A = relu(g_B) @ W1 (tf32); agg g_A -> g_B ----
    gemm_tf32_kernel<<<wmma_grid, 256>>>(nullptr, W1, NN, 1, /*in_sel=*/1);
    agg256_kernel<<<agg_grid, 256>>>(b1);

    // ---- layer 2: g_C40 = relu(g_B) @ W2; agg g_C40 -> g_D40 ----
    gemm_small_kernel<<<small_grid, 256>>>(W2, NN, NC);
    agg40_kernel<<<agg_grid, 256>>>(b2);

    // ---- log_softmax: g_D40 -> out ----
    log_softmax_kernel<<<(NN * 32 + 255) / 256, 256>>>(out);
}

// round 16
// speedup vs baseline: 1.1472x; 1.1472x over previous
#include <cuda_runtime.h>
#include <cuda_bf16.h>
#include <math.h>
#include <stdint.h>

#define NN 50000
#define NE 800000
#define DH 256
#define NC 40
#define NB_SCAN ((NN + 1023) / 1024)  // 49

// ---------------- device scratch ----------------
__device__ int   g_cnt[NN];
__device__ int   g_ptr[NN + 1];
__device__ int   g_cur[NN];
__device__ int   g_srcs[NE];
__device__ int   g_bsum[64];
__device__ int   g_boff[64];
__device__ float g_dis[NN];
__device__ float g_A[(size_t)NN * DH];    // GEMM out (layers 0,1)
__device__ float g_B[(size_t)NN * DH];    // aggregation out, RELU'd (layers 0,1)
__device__ float g_C40[(size_t)NN * NC];  // layer-2 GEMM out

// ---------------- CSR build (edge_index int32: row 0 = src, row 1 = dst) ----------------
__global__ void zero_cnt_kernel() {
    int i = blockIdx.x * blockDim.x + threadIdx.x;
    if (i < NN) g_cnt[i] = 0;
}

__global__ void count_deg_kernel(const int* __restrict__ ei) {
    int e = blockIdx.x * blockDim.x + threadIdx.x;
    if (e < NE) {
        int d = ei[NE + e];
        if (d >= 0 && d < NN) atomicAdd(&g_cnt[d], 1);
    }
}

// phase 1: per-block (1024) exclusive scan via shuffles; block totals to g_bsum
__global__ __launch_bounds__(1024) void scan1_kernel() {
    int tid = threadIdx.x;
    int b = blockIdx.x;
    int i = b * 1024 + tid;
    int v = (i < NN) ? g_cnt[i] : 0;
    int lane = tid & 31, wid = tid >> 5;
    int incl = v;
#pragma unroll
    for (int o = 1; o < 32; o <<= 1) {
        int t = __shfl_up_sync(0xFFFFFFFFu, incl, o);
        if (lane >= o) incl += t;
    }
    __shared__ int ws[32];
    if (lane == 31) ws[wid] = incl;
    __syncthreads();
    if (wid == 0) {
        int wv = ws[lane];
#pragma unroll
        for (int o = 1; o < 32; o <<= 1) {
            int t = __shfl_up_sync(0xFFFFFFFFu, wv, o);
            if (lane >= o) wv += t;
        }
        ws[lane] = wv;
    }
    __syncthreads();
    int woff = wid ? ws[wid - 1] : 0;
    int excl = woff + incl - v;
    if (i < NN) {
        g_ptr[i] = excl;                       // block-local exclusive; offset added in phase 3
        g_dis[i] = rsqrtf((float)(v + 1));     // +1 self loop
    }
    if (tid == 1023) g_bsum[b] = woff + incl;  // block total
}

// phase 2: scan the 49 block sums (64 threads = 2 warps)
__global__ void scan2_kernel() {
    int tid = threadIdx.x;  // 0..63
    int v = (tid < NB_SCAN) ? g_bsum[tid] : 0;
    int lane = tid & 31, wid = tid >> 5;
    int incl = v;
#pragma unroll
    for (int o = 1; o < 32; o <<= 1) {
        int t = __shfl_up_sync(0xFFFFFFFFu, incl, o);
        if (lane >= o) incl += t;
    }
    __shared__ int ws[2];
    if (lane == 31) ws[wid] = incl;
    __syncthreads();
    int woff = (wid == 1) ? ws[0] : 0;
    int excl = woff + incl - v;
    if (tid < NB_SCAN) g_boff[tid] = excl;
    if (tid == NB_SCAN - 1) g_ptr[NN] = excl + v;
}

// phase 3: add block offsets
__global__ void scan3_kernel() {
    int i = blockIdx.x * blockDim.x + threadIdx.x;
    if (i < NN) {
        int p = g_ptr[i] + g_boff[i >> 10];
        g_ptr[i] = p;
        g_cur[i] = p;
    }
}

__global__ void scatter_kernel(const int* __restrict__ ei) {
    int e = blockIdx.x * blockDim.x + threadIdx.x;
    if (e < NE) {
        int d = ei[NE + e];
        int srcv = ei[e];
        if (d >= 0 && d < NN && srcv >= 0 && srcv < NN) {
            int pos = atomicAdd(&g_cur[d], 1);
            g_srcs[pos] = srcv;
        }
    }
}

// ---------------- pipelined SIMT GEMM: C[M,N] = A[M,256] @ W[256,N] ----------------
// 128x128(or N) tile, 256 threads, 8x8/thread, BK=16, 2-stage smem + register prefetch.
// in_sel: 0 -> A = xext, 1 -> A = g_B (already relu'd). out_sel: 0 -> g_A, 1 -> g_C40.
__global__ __launch_bounds__(256)
void gemm_kernel(const float* __restrict__ xext, const float* __restrict__ W,
                 int M, int N, int in_sel, int out_sel) {
    const int K = DH;
    const float* A = in_sel ? (const float*)g_B : xext;
    float* C = out_sel ? (float*)g_C40 : (float*)g_A;

    __shared__ float As[2][16][128];  // k-major
    __shared__ float Bs[2][16][128];

    int tid = threadIdx.x;
    int bm = blockIdx.y * 128;
    int bn = blockIdx.x * 128;
    int tx = tid & 15;
    int ty = tid >> 4;

    // per-thread load coords (2 float4 each for A and B)
    int arow[2], akc[2], bkr[2], bcol[2];
#pragma unroll
    for (int l = 0; l < 2; l++) {
        int f = tid * 2 + l;
        arow[l] = f >> 2;
        akc[l] = (f & 3) * 4;
        bkr[l] = f >> 5;
        bcol[l] = (f & 31) * 4;
    }

    float acc[8][8];
#pragma unroll
    for (int i = 0; i < 8; i++)
#pragma unroll
        for (int j = 0; j < 8; j++) acc[i][j] = 0.0f;

    // prologue: tile 0 straight to smem buffer 0
#pragma unroll
    for (int l = 0; l < 2; l++) {
        int grow = bm + arow[l];
        float4 v = make_float4(0.f, 0.f, 0.f, 0.f);
        if (grow < M) v = *(const float4*)(A + (size_t)grow * K + akc[l]);
        As[0][akc[l] + 0][arow[l]] = v.x;
        As[0][akc[l] + 1][arow[l]] = v.y;
        As[0][akc[l] + 2][arow[l]] = v.z;
        As[0][akc[l] + 3][arow[l]] = v.w;
        int gc = bn + bcol[l];
        float4 w = make_float4(0.f, 0.f, 0.f, 0.f);
        if (gc + 3 < N) w = *(const float4*)(W + (size_t)bkr[l] * N + gc);
        *(float4*)&Bs[0][bkr[l]][bcol[l]] = w;
    }
    __syncthreads();

    const int NIT = K / 16;  // 16
    float4 pa[2], pb[2];
    for (int it = 0; it < NIT; it++) {
        int cur = it & 1;
        bool more = (it + 1 < NIT);
        if (more) {
            int ktn = (it + 1) * 16;
#pragma unroll
            for (int l = 0; l < 2; l++) {
                int grow = bm + arow[l];
                pa[l] = make_float4(0.f, 0.f, 0.f, 0.f);
                if (grow < M) pa[l] = *(const float4*)(A + (size_t)grow * K + ktn + akc[l]);
                int gc = bn + bcol[l];
                pb[l] = make_float4(0.f, 0.f, 0.f, 0.f);
                if (gc + 3 < N) pb[l] = *(const float4*)(W + (size_t)(ktn + bkr[l]) * N + gc);
            }
        }

#pragma unroll
        for (int kk = 0; kk < 16; kk++) {
            float a[8], b[8];
            *(float4*)&a[0] = *(float4*)&As[cur][kk][ty * 8];
            *(float4*)&a[4] = *(float4*)&As[cur][kk][ty * 8 + 4];
            *(float4*)&b[0] = *(float4*)&Bs[cur][kk][tx * 8];
            *(float4*)&b[4] = *(float4*)&Bs[cur][kk][tx * 8 + 4];
#pragma unroll
            for (int i = 0; i < 8; i++)
#pragma unroll
                for (int j = 0; j < 8; j++) acc[i][j] += a[i] * b[j];
        }

        if (more) {
            int nxt = 1 - cur;
#pragma unroll
            for (int l = 0; l < 2; l++) {
                As[nxt][akc[l] + 0][arow[l]] = pa[l].x;
                As[nxt][akc[l] + 1][arow[l]] = pa[l].y;
                As[nxt][akc[l] + 2][arow[l]] = pa[l].z;
                As[nxt][akc[l] + 3][arow[l]] = pa[l].w;
                *(float4*)&Bs[nxt][bkr[l]][bcol[l]] = pb[l];
            }
            __syncthreads();
        }
    }

#pragma unroll
    for (int i = 0; i < 8; i++) {
        int r = bm + ty * 8 + i;
        if (r >= M) continue;
#pragma unroll
        for (int j = 0; j < 8; j += 4) {
            int c = bn + tx * 8 + j;
            if (c + 3 < N) {
                float4 v = make_float4(acc[i][j], acc[i][j + 1], acc[i][j + 2], acc[i][j + 3]);
                *(float4*)(C + (size_t)r * N + c) = v;
            }
        }
    }
}

// ---------------- aggregation (gather) + bias + RELU: g_B = relu(Â(g_A) + b) ----------------
__global__ __launch_bounds__(256)
void agg256_kernel(const float* __restrict__ bias) {
    const float* xw = (const float*)g_A;
    float* out = (float*)g_B;
    int node = blockIdx.x * (blockDim.x >> 5) + (threadIdx.x >> 5);
    int lane = threadIdx.x & 31;
    if (node >= NN) return;
    int beg = g_ptr[node], end = g_ptr[node + 1];
    float dd = g_dis[node];

    float4 acc0 = make_float4(0.f, 0.f, 0.f, 0.f);
    float4 acc1 = make_float4(0.f, 0.f, 0.f, 0.f);
    for (int i = beg; i < end; i++) {
        int s = g_srcs[i];
        float nrm = g_dis[s] * dd;
        const float4* row = (const float4*)(xw + (size_t)s * DH);
        float4 a = row[lane];
        float4 b = row[lane + 32];
        acc0.x += nrm * a.x; acc0.y += nrm * a.y; acc0.z += nrm * a.z; acc0.w += nrm * a.w;
        acc1.x += nrm * b.x; acc1.y += nrm * b.y; acc1.z += nrm * b.z; acc1.w += nrm * b.w;
    }
    {
        float self = dd * dd;
        const float4* row = (const float4*)(xw + (size_t)node * DH);
        float4 a = row[lane];
        float4 b = row[lane + 32];
        acc0.x += self * a.x; acc0.y += self * a.y; acc0.z += self * a.z; acc0.w += self * a.w;
        acc1.x += self * b.x; acc1.y += self * b.y; acc1.z += self * b.z; acc1.w += self * b.w;
    }
    const float4* bb = (const float4*)bias;
    float4 b0 = bb[lane], b1 = bb[lane + 32];
    // relu(agg + bias) fused
    acc0.x = fmaxf(acc0.x + b0.x, 0.f); acc0.y = fmaxf(acc0.y + b0.y, 0.f);
    acc0.z = fmaxf(acc0.z + b0.z, 0.f); acc0.w = fmaxf(acc0.w + b0.w, 0.f);
    acc1.x = fmaxf(acc1.x + b1.x, 0.f); acc1.y = fmaxf(acc1.y + b1.y, 0.f);
    acc1.z = fmaxf(acc1.z + b1.z, 0.f); acc1.w = fmaxf(acc1.w + b1.w, 0.f);
    float4* o = (float4*)(out + (size_t)node * DH);
    o[lane] = acc0;
    o[lane + 32] = acc1;
}

// ---------------- layer-2 aggregation + bias + log_softmax fused; writes d_out ----------------
__global__ __launch_bounds__(256)
void agg40sm_kernel(const float* __restrict__ bias, float* __restrict__ out) {
    const float* xw = (const float*)g_C40;
    int node = blockIdx.x * (blockDim.x >> 5) + (threadIdx.x >> 5);
    int lane = threadIdx.x & 31;
    if (node >= NN) return;
    int beg = g_ptr[node], end = g_ptr[node + 1];
    float dd = g_dis[node];
    bool hi = (lane < NC - 32);

    float a0 = 0.f, a1 = 0.f;
    for (int i = beg; i < end; i++) {
        int s = g_srcs[i];
        float nrm = g_dis[s] * dd;
        const float* row = xw + (size_t)s * NC;
        a0 += nrm * row[lane];
        if (hi) a1 += nrm * row[32 + lane];
    }
    {
        float self = dd * dd;
        const float* row = xw + (size_t)node * NC;
        a0 += self * row[lane];
        if (hi) a1 += self * row[32 + lane];
    }
    a0 += bias[lane];
    if (hi) a1 += bias[32 + lane];

    // log_softmax over the 40 values held by this warp
    float mx = hi ? fmaxf(a0, a1) : a0;
#pragma unroll
    for (int o = 16; o > 0; o >>= 1) mx = fmaxf(mx, __shfl_xor_sync(0xFFFFFFFF, mx, o));
    float s = expf(a0 - mx) + (hi ? expf(a1 - mx) : 0.f);
#pragma unroll
    for (int o = 16; o > 0; o >>= 1) s += __shfl_xor_sync(0xFFFFFFFF, s, o);
    float lse = mx + logf(s);
    float* w = out + (size_t)node * NC;
    w[lane] = a0 - lse;
    if (hi) w[32 + lane] = a1 - lse;
}

// ---------------- launch ----------------
extern "C" void kernel_launch(void* const* d_in, const int* in_sizes, int n_in,
                              void* d_out, int out_size) {
    const float* x = (const float*)d_in[0];
    const int* ei = (const int*)d_in[1];   // int32 (JAX demotes int64 without x64)
    const float* W0 = (const float*)d_in[2];
    const float* b0 = (const float*)d_in[3];
    const float* W1 = (const float*)d_in[4];
    const float* b1 = (const float*)d_in[5];
    const float* W2 = (const float*)d_in[6];
    const float* b2 = (const float*)d_in[7];
    float* out = (float*)d_out;

    // CSR build + normalization
    zero_cnt_kernel<<<(NN + 255) / 256, 256>>>();
    count_deg_kernel<<<(NE + 255) / 256, 256>>>(ei);
    scan1_kernel<<<NB_SCAN, 1024>>>();
    scan2_kernel<<<1, 64>>>();
    scan3_kernel<<<(NN + 255) / 256, 256>>>();
    scatter_kernel<<<(NE + 255) / 256, 256>>>(ei);

    dim3 gemm_grid_big(DH / 128, (NN + 127) / 128);
    dim3 gemm_grid_small(1, (NN + 127) / 128);
    int agg_grid = (NN + 7) / 8;

    // ---- layer 0: g_A = x @ W0; g_B = relu(agg(g_A) + b0) ----
    gemm_kernel<<<gemm_grid_big, 256>>>(x, W0, NN, DH, /*in_sel=*/0, /*out_sel=*/0);
    agg256_kernel<<<agg_grid, 256>>>(b0);

    // ---- layer 1: g_A = g_B @ W1; g_B = relu(agg(g_A) + b1) ----
    gemm_kernel<<<gemm_grid_big, 256>>>(nullptr, W1, NN, DH, /*in_sel=*/1, /*out_sel=*/0);
    agg256_kernel<<<agg_grid, 256>>>(b1);

    // ---- layer 2: g_C40 = g_B @ W2; out = log_softmax(agg(g_C40) + b2) ----
    gemm_kernel<<<gemm_grid_small, 256>>>(nullptr, W2, NN, NC, /*in_sel=*/1, /*out_sel=*/1);
    agg40sm_kernel<<<agg_grid, 256>>>(b2, out);
}

// round 17
// speedup vs baseline: 1.3802x; 1.2031x over previous
#include <cuda_runtime.h>
#include <cuda_bf16.h>
#include <math.h>
#include <stdint.h>

#define NN 50000
#define NE 800000
#define DH 256
#define NC 40
#define NB_SCAN ((NN + 1023) / 1024)  // 49

// ---------------- device scratch ----------------
__device__ int   g_cnt[NN];
__device__ int   g_ptr[NN + 1];
__device__ int   g_cur[NN];
__device__ int   g_srcs[NE];
__device__ int   g_bsum[64];
__device__ int   g_boff[64];
__device__ float g_dis[NN];
__device__ float g_A[(size_t)NN * DH];    // GEMM out (layers 0,1)
__device__ float g_B[(size_t)NN * DH];    // aggregation out, RELU'd (layers 0,1)
__device__ float g_C40[(size_t)NN * NC];  // layer-2 GEMM out

// ---------------- CSR build (edge_index int32: row 0 = src, row 1 = dst) ----------------
__global__ void zero_cnt_kernel() {
    int i = blockIdx.x * blockDim.x + threadIdx.x;
    if (i < NN) g_cnt[i] = 0;
}

__global__ void count_deg_kernel(const int* __restrict__ ei) {
    int e = blockIdx.x * blockDim.x + threadIdx.x;
    if (e < NE) {
        int d = ei[NE + e];
        if (d >= 0 && d < NN) atomicAdd(&g_cnt[d], 1);
    }
}

// phase 1: per-block (1024) exclusive scan via shuffles; block totals to g_bsum
__global__ __launch_bounds__(1024) void scan1_kernel() {
    int tid = threadIdx.x;
    int b = blockIdx.x;
    int i = b * 1024 + tid;
    int v = (i < NN) ? g_cnt[i] : 0;
    int lane = tid & 31, wid = tid >> 5;
    int incl = v;
#pragma unroll
    for (int o = 1; o < 32; o <<= 1) {
        int t = __shfl_up_sync(0xFFFFFFFFu, incl, o);
        if (lane >= o) incl += t;
    }
    __shared__ int ws[32];
    if (lane == 31) ws[wid] = incl;
    __syncthreads();
    if (wid == 0) {
        int wv = ws[lane];
#pragma unroll
        for (int o = 1; o < 32; o <<= 1) {
            int t = __shfl_up_sync(0xFFFFFFFFu, wv, o);
            if (lane >= o) wv += t;
        }
        ws[lane] = wv;
    }
    __syncthreads();
    int woff = wid ? ws[wid - 1] : 0;
    int excl = woff + incl - v;
    if (i < NN) {
        g_ptr[i] = excl;                       // block-local exclusive; offset added in phase 3
        g_dis[i] = rsqrtf((float)(v + 1));     // +1 self loop
    }
    if (tid == 1023) g_bsum[b] = woff + incl;  // block total
}

// phase 2: scan the 49 block sums
__global__ void scan2_kernel() {
    int tid = threadIdx.x;  // 0..63
    int v = (tid < NB_SCAN) ? g_bsum[tid] : 0;
    int lane = tid & 31, wid = tid >> 5;
    int incl = v;
#pragma unroll
    for (int o = 1; o < 32; o <<= 1) {
        int t = __shfl_up_sync(0xFFFFFFFFu, incl, o);
        if (lane >= o) incl += t;
    }
    __shared__ int ws[2];
    if (lane == 31) ws[wid] = incl;
    __syncthreads();
    int woff = (wid == 1) ? ws[0] : 0;
    int excl = woff + incl - v;
    if (tid < NB_SCAN) g_boff[tid] = excl;
    if (tid == NB_SCAN - 1) g_ptr[NN] = excl + v;
}

// phase 3: add block offsets
__global__ void scan3_kernel() {
    int i = blockIdx.x * blockDim.x + threadIdx.x;
    if (i < NN) {
        int p = g_ptr[i] + g_boff[i >> 10];
        g_ptr[i] = p;
        g_cur[i] = p;
    }
}

__global__ void scatter_kernel(const int* __restrict__ ei) {
    int e = blockIdx.x * blockDim.x + threadIdx.x;
    if (e < NE) {
        int d = ei[NE + e];
        int srcv = ei[e];
        if (d >= 0 && d < NN && srcv >= 0 && srcv < NN) {
            int pos = atomicAdd(&g_cur[d], 1);
            g_srcs[pos] = srcv;
        }
    }
}

// ---------------- packed-f32x2 helpers ----------------
__device__ __forceinline__ uint64_t pack2(float lo, float hi) {
    uint64_t r;
    asm("mov.b64 %0, {%1, %2};" : "=l"(r) : "f"(lo), "f"(hi));
    return r;
}
__device__ __forceinline__ uint64_t dup2(float v) {
    uint64_t r;
    asm("mov.b64 %0, {%1, %1};" : "=l"(r) : "f"(v));
    return r;
}
__device__ __forceinline__ void fma2(uint64_t& d, uint64_t a, uint64_t b) {
    asm("fma.rn.f32x2 %0, %1, %2, %0;" : "+l"(d) : "l"(a), "l"(b));
}
__device__ __forceinline__ void unpack2(uint64_t p, float& lo, float& hi) {
    asm("mov.b64 {%0, %1}, %2;" : "=f"(lo), "=f"(hi) : "l"(p));
}

// ---------------- pipelined SIMT GEMM (FFMA2): C[M,N] = A[M,256] @ W[256,N] ----------------
// 128x128(or N) tile, 256 threads, 8x8/thread, BK=16, 2-stage smem + register prefetch.
// in_sel: 0 -> A = xext, 1 -> A = g_B (already relu'd). out_sel: 0 -> g_A, 1 -> g_C40.
__global__ __launch_bounds__(256)
void gemm_kernel(const float* __restrict__ xext, const float* __restrict__ W,
                 int M, int N, int in_sel, int out_sel) {
    const int K = DH;
    const float* A = in_sel ? (const float*)g_B : xext;
    float* C = out_sel ? (float*)g_C40 : (float*)g_A;

    __shared__ float As[2][16][128];  // k-major
    __shared__ float Bs[2][16][128];

    int tid = threadIdx.x;
    int bm = blockIdx.y * 128;
    int bn = blockIdx.x * 128;
    int tx = tid & 15;
    int ty = tid >> 4;

    int arow[2], akc[2], bkr[2], bcol[2];
#pragma unroll
    for (int l = 0; l < 2; l++) {
        int f = tid * 2 + l;
        arow[l] = f >> 2;
        akc[l] = (f & 3) * 4;
        bkr[l] = f >> 5;
        bcol[l] = (f & 31) * 4;
    }

    // packed accumulators: acc2[i][j] = (C[i][2j], C[i][2j+1])
    uint64_t acc2[8][4];
#pragma unroll
    for (int i = 0; i < 8; i++)
#pragma unroll
        for (int j = 0; j < 4; j++) acc2[i][j] = 0ull;

    // prologue: tile 0 straight to smem buffer 0
#pragma unroll
    for (int l = 0; l < 2; l++) {
        int grow = bm + arow[l];
        float4 v = make_float4(0.f, 0.f, 0.f, 0.f);
        if (grow < M) v = *(const float4*)(A + (size_t)grow * K + akc[l]);
        As[0][akc[l] + 0][arow[l]] = v.x;
        As[0][akc[l] + 1][arow[l]] = v.y;
        As[0][akc[l] + 2][arow[l]] = v.z;
        As[0][akc[l] + 3][arow[l]] = v.w;
        int gc = bn + bcol[l];
        float4 w = make_float4(0.f, 0.f, 0.f, 0.f);
        if (gc + 3 < N) w = *(const float4*)(W + (size_t)bkr[l] * N + gc);
        *(float4*)&Bs[0][bkr[l]][bcol[l]] = w;
    }
    __syncthreads();

    const int NIT = K / 16;  // 16
    float4 pa[2], pb[2];
    for (int it = 0; it < NIT; it++) {
        int cur = it & 1;
        bool more = (it + 1 < NIT);
        if (more) {
            int ktn = (it + 1) * 16;
#pragma unroll
            for (int l = 0; l < 2; l++) {
                int grow = bm + arow[l];
                pa[l] = make_float4(0.f, 0.f, 0.f, 0.f);
                if (grow < M) pa[l] = *(const float4*)(A + (size_t)grow * K + ktn + akc[l]);
                int gc = bn + bcol[l];
                pb[l] = make_float4(0.f, 0.f, 0.f, 0.f);
                if (gc + 3 < N) pb[l] = *(const float4*)(W + (size_t)(ktn + bkr[l]) * N + gc);
            }
        }

#pragma unroll
        for (int kk = 0; kk < 16; kk++) {
            float a[8], b[8];
            *(float4*)&a[0] = *(float4*)&As[cur][kk][ty * 8];
            *(float4*)&a[4] = *(float4*)&As[cur][kk][ty * 8 + 4];
            *(float4*)&b[0] = *(float4*)&Bs[cur][kk][tx * 8];
            *(float4*)&b[4] = *(float4*)&Bs[cur][kk][tx * 8 + 4];
            uint64_t bp[4];
#pragma unroll
            for (int j = 0; j < 4; j++) bp[j] = pack2(b[2 * j], b[2 * j + 1]);
#pragma unroll
            for (int i = 0; i < 8; i++) {
                uint64_t ad = dup2(a[i]);
#pragma unroll
                for (int j = 0; j < 4; j++) fma2(acc2[i][j], ad, bp[j]);
            }
        }

        if (more) {
            int nxt = 1 - cur;
#pragma unroll
            for (int l = 0; l < 2; l++) {
                As[nxt][akc[l] + 0][arow[l]] = pa[l].x;
                As[nxt][akc[l] + 1][arow[l]] = pa[l].y;
                As[nxt][akc[l] + 2][arow[l]] = pa[l].z;
                As[nxt][akc[l] + 3][arow[l]] = pa[l].w;
                *(float4*)&Bs[nxt][bkr[l]][bcol[l]] = pb[l];
            }
            __syncthreads();
        }
    }

#pragma unroll
    for (int i = 0; i < 8; i++) {
        int r = bm + ty * 8 + i;
        if (r >= M) continue;
#pragma unroll
        for (int j = 0; j < 8; j += 4) {
            int c = bn + tx * 8 + j;
            if (c + 3 < N) {
                float4 v;
                unpack2(acc2[i][j / 2], v.x, v.y);
                unpack2(acc2[i][j / 2 + 1], v.z, v.w);
                *(float4*)(C + (size_t)r * N + c) = v;
            }
        }
    }
}

// ---------------- aggregation (gather) + bias + RELU: g_B = relu(Â(g_A) + b) ----------------
__global__ __launch_bounds__(256)
void agg256_kernel(const float* __restrict__ bias) {
    const float* xw = (const float*)g_A;
    float* out = (float*)g_B;
    int node = blockIdx.x * (blockDim.x >> 5) + (threadIdx.x >> 5);
    int lane = threadIdx.x & 31;
    if (node >= NN) return;
    int beg = g_ptr[node], end = g_ptr[node + 1];
    float dd = g_dis[node];

    float4 acc0 = make_float4(0.f, 0.f, 0.f, 0.f);
    float4 acc1 = make_float4(0.f, 0.f, 0.f, 0.f);
    for (int i = beg; i < end; i++) {
        int s = g_srcs[i];
        float nrm = g_dis[s] * dd;
        const float4* row = (const float4*)(xw + (size_t)s * DH);
        float4 a = row[lane];
        float4 b = row[lane + 32];
        acc0.x += nrm * a.x; acc0.y += nrm * a.y; acc0.z += nrm * a.z; acc0.w += nrm * a.w;
        acc1.x += nrm * b.x; acc1.y += nrm * b.y; acc1.z += nrm * b.z; acc1.w += nrm * b.w;
    }
    {
        float self = dd * dd;
        const float4* row = (const float4*)(xw + (size_t)node * DH);
        float4 a = row[lane];
        float4 b = row[lane + 32];
        acc0.x += self * a.x; acc0.y += self * a.y; acc0.z += self * a.z; acc0.w += self * a.w;
        acc1.x += self * b.x; acc1.y += self * b.y; acc1.z += self * b.z; acc1.w += self * b.w;
    }
    const float4* bb = (const float4*)bias;
    float4 b0 = bb[lane], b1 = bb[lane + 32];
    acc0.x = fmaxf(acc0.x + b0.x, 0.f); acc0.y = fmaxf(acc0.y + b0.y, 0.f);
    acc0.z = fmaxf(acc0.z + b0.z, 0.f); acc0.w = fmaxf(acc0.w + b0.w, 0.f);
    acc1.x = fmaxf(acc1.x + b1.x, 0.f); acc1.y = fmaxf(acc1.y + b1.y, 0.f);
    acc1.z = fmaxf(acc1.z + b1.z, 0.f); acc1.w = fmaxf(acc1.w + b1.w, 0.f);
    float4* o = (float4*)(out + (size_t)node * DH);
    o[lane] = acc0;
    o[lane + 32] = acc1;
}

// ---------------- layer-2 aggregation + bias + log_softmax fused; writes d_out ----------------
__global__ __launch_bounds__(256)
void agg40sm_kernel(const float* __restrict__ bias, float* __restrict__ out) {
    const float* xw = (const float*)g_C40;
    int node = blockIdx.x * (blockDim.x >> 5) + (threadIdx.x >> 5);
    int lane = threadIdx.x & 31;
    if (node >= NN) return;
    int beg = g_ptr[node], end = g_ptr[node + 1];
    float dd = g_dis[node];
    bool hi = (lane < NC - 32);

    float a0 = 0.f, a1 = 0.f;
    for (int i = beg; i < end; i++) {
        int s = g_srcs[i];
        float nrm = g_dis[s] * dd;
        const float* row = xw + (size_t)s * NC;
        a0 += nrm * row[lane];
        if (hi) a1 += nrm * row[32 + lane];
    }
    {
        float self = dd * dd;
        const float* row = xw + (size_t)node * NC;
        a0 += self * row[lane];
        if (hi) a1 += self * row[32 + lane];
    }
    a0 += bias[lane];
    if (hi) a1 += bias[32 + lane];

    float mx = hi ? fmaxf(a0, a1) : a0;
#pragma unroll
    for (int o = 16; o > 0; o >>= 1) mx = fmaxf(mx, __shfl_xor_sync(0xFFFFFFFF, mx, o));
    float s = expf(a0 - mx) + (hi ? expf(a1 - mx) : 0.f);
#pragma unroll
    for (int o = 16; o > 0; o >>= 1) s += __shfl_xor_sync(0xFFFFFFFF, s, o);
    float lse = mx + logf(s);
    float* w = out + (size_t)node * NC;
    w[lane] = a0 - lse;
    if (hi) w[32 + lane] = a1 - lse;
}

// ---------------- launch ----------------
extern "C" void kernel_launch(void* const* d_in, const int* in_sizes, int n_in,
                              void* d_out, int out_size) {
    const float* x = (const float*)d_in[0];
    const int* ei = (const int*)d_in[1];   // int32 (JAX demotes int64 without x64)
    const float* W0 = (const float*)d_in[2];
    const float* b0 = (const float*)d_in[3];
    const float* W1 = (const float*)d_in[4];
    const float* b1 = (const float*)d_in[5];
    const float* W2 = (const float*)d_in[6];
    const float* b2 = (const float*)d_in[7];
    float* out = (float*)d_out;

    // CSR build + normalization
    zero_cnt_kernel<<<(NN + 255) / 256, 256>>>();
    count_deg_kernel<<<(NE + 255) / 256, 256>>>(ei);
    scan1_kernel<<<NB_SCAN, 1024>>>();
    scan2_kernel<<<1, 64>>>();
    scan3_kernel<<<(NN + 255) / 256, 256>>>();
    scatter_kernel<<<(NE + 255) / 256, 256>>>(ei);

    dim3 gemm_grid_big(DH / 128, (NN + 127) / 128);
    dim3 gemm_grid_small(1, (NN + 127) / 128);
    int agg_grid = (NN + 7) / 8;

    // ---- layer 0: g_A = x @ W0; g_B = relu(agg(g_A) + b0) ----
    gemm_kernel<<<gemm_grid_big, 256>>>(x, W0, NN, DH, /*in_sel=*/0, /*out_sel=*/0);
    agg256_kernel<<<agg_grid, 256>>>(b0);

    // ---- layer 1: g_A = g_B @ W1; g_B = relu(agg(g_A) + b1) ----
    gemm_kernel<<<gemm_grid_big, 256>>>(nullptr, W1, NN, DH, /*in_sel=*/1, /*out_sel=*/0);
    agg256_kernel<<<agg_grid, 256>>>(b1);

    // ---- layer 2: g_C40 = g_B @ W2; out = log_softmax(agg(g_C40) + b2) ----
    gemm_kernel<<<gemm_grid_small, 256>>>(nullptr, W2, NN, NC, /*in_sel=*/1, /*out_sel=*/1);
    agg40sm_kernel<<<agg_grid, 256>>>(b2, out);
}